// round 5
// baseline (speedup 1.0000x reference)
#include <cuda_runtime.h>

// ---------------------------------------------------------------------------
// SpikingNeuralNetwork: 100-step LIF sim. Dense fp32 GEMMs accumulated in
// kc=512 depth blocks (Eigen gebp order: per-element ascending-k FMA chain
// within each 512-block, block partials added sequentially), matching the
// XLA-CPU/Eigen reference. Elementwise math strictly rounded.
// B=128, In=1024, H=4096, Out=1024, T=100.
// ---------------------------------------------------------------------------

#define Bsz  128
#define In_  1024
#define Hd_  4096
#define Out_ 1024
#define T_   100
#define KC   512

#define THRESH 1.0f
#define DECAY  0.95f
#define REFRAC 2.0f
#define LR     0.001f

// -------------------- persistent device state -------------------------------
__device__ float g_vi[Bsz * In_];
__device__ float g_ri[Bsz * In_];
__device__ float g_vh[Bsz * Hd_];
__device__ float g_rh[Bsz * Hd_];
__device__ float g_vo[Bsz * Out_];
__device__ float g_ro[Bsz * Out_];
__device__ float g_W1[Hd_ * In_];
__device__ float g_in_spk[Bsz * In_];
__device__ float g_hid_spk[Bsz * Hd_];
__device__ float g_tp[In_];
__device__ float g_tn[Hd_];
__device__ float g_pre[In_];
__device__ float g_post[Hd_];
__device__ float g_both[1];

// -------------------- LIF: strictly rounded (no FMA contraction) -----------
__device__ __forceinline__ float lif_step(float I, float& v, float& r) {
    bool active = I > 0.0f;
    bool refrac = r > 0.0f;
    float v_int = __fadd_rn(__fmul_rn(v, DECAY), I);
    bool fired = active && !refrac && (v_int >= THRESH);
    float v_new = !active ? v : ((refrac || fired) ? 0.0f : v_int);
    float r_new = !active ? r : (refrac ? __fsub_rn(r, 1.0f) : (fired ? REFRAC : r));
    v = v_new;
    r = r_new;
    return fired ? 1.0f : 0.0f;
}

// -------------------- init ---------------------------------------------------
__global__ void k_init(float* __restrict__ out) {
    int idx = blockIdx.x * blockDim.x + threadIdx.x;   // covers Bsz*Hd_
    if (idx < Bsz * In_)  { g_vi[idx] = 0.0f; g_ri[idx] = 0.0f; g_in_spk[idx] = 0.0f; }
    if (idx < Bsz * Out_) { g_vo[idx] = 0.0f; g_ro[idx] = 0.0f; out[idx] = 0.0f; }
    if (idx < Bsz * Hd_)  { g_vh[idx] = 0.0f; g_rh[idx] = 0.0f; }
    if (idx < In_) g_tp[idx] = 0.0f;
    if (idx < Hd_) g_tn[idx] = 0.0f;
    if (idx == 0)  g_both[0] = 0.0f;
}

__global__ void k_copyW1(const float* __restrict__ W1) {
    int idx = blockIdx.x * blockDim.x + threadIdx.x;
    g_W1[idx] = W1[idx];
}

// -------------------- encode + input-layer LIF ------------------------------
__global__ void k_input(const float* __restrict__ x,
                        const float* __restrict__ noise_t) {
    int idx = blockIdx.x * blockDim.x + threadIdx.x;   // Bsz*In_
    float p = fminf(fmaxf(__fmul_rn(x[idx], 100.0f), 0.0f), 100.0f);
    p = __fmul_rn(p, 0.001f);
    float I = (noise_t[idx] < p) ? 1.0f : 0.0f;
    float v = g_vi[idx], r = g_ri[idx];
    float spk = lif_step(I, v, r);
    g_vi[idx] = v; g_ri[idx] = r; g_in_spk[idx] = spk;
}

// -------------------- hidden GEMM (64x64 tile, BK=16) + fused LIF -----------
#define BM 64
#define BN 64
#define BK 16

__global__ __launch_bounds__(256) void k_gemm_hid_lif() {
    __shared__ float As[BK][BM + 1];
    __shared__ float Bs[BK][BN + 1];
    const int bn = blockIdx.x * BN;     // over Hd_
    const int bm = blockIdx.y * BM;     // over Bsz
    const int tid = threadIdx.x;
    const int tx = tid & 15;
    const int ty = tid >> 4;
    float tot[4][4] = {};
    float acc[4][4] = {};

    for (int k0 = 0; k0 < In_; k0 += BK) {
#pragma unroll
        for (int p = 0; p < 4; p++) {
            int e = p * 256 + tid;
            int m = e >> 4, k = e & 15;
            As[k][m] = g_in_spk[(bm + m) * In_ + k0 + k];
        }
#pragma unroll
        for (int p = 0; p < 4; p++) {
            int e = p * 256 + tid;
            int n = e >> 4, k = e & 15;
            Bs[k][n] = g_W1[(bn + n) * In_ + k0 + k];
        }
        __syncthreads();
#pragma unroll
        for (int k = 0; k < BK; k++) {
            float a0 = As[k][ty * 4 + 0], a1 = As[k][ty * 4 + 1];
            float a2 = As[k][ty * 4 + 2], a3 = As[k][ty * 4 + 3];
            float b0 = Bs[k][tx * 4 + 0], b1 = Bs[k][tx * 4 + 1];
            float b2 = Bs[k][tx * 4 + 2], b3 = Bs[k][tx * 4 + 3];
            acc[0][0] = __fmaf_rn(a0, b0, acc[0][0]); acc[0][1] = __fmaf_rn(a0, b1, acc[0][1]);
            acc[0][2] = __fmaf_rn(a0, b2, acc[0][2]); acc[0][3] = __fmaf_rn(a0, b3, acc[0][3]);
            acc[1][0] = __fmaf_rn(a1, b0, acc[1][0]); acc[1][1] = __fmaf_rn(a1, b1, acc[1][1]);
            acc[1][2] = __fmaf_rn(a1, b2, acc[1][2]); acc[1][3] = __fmaf_rn(a1, b3, acc[1][3]);
            acc[2][0] = __fmaf_rn(a2, b0, acc[2][0]); acc[2][1] = __fmaf_rn(a2, b1, acc[2][1]);
            acc[2][2] = __fmaf_rn(a2, b2, acc[2][2]); acc[2][3] = __fmaf_rn(a2, b3, acc[2][3]);
            acc[3][0] = __fmaf_rn(a3, b0, acc[3][0]); acc[3][1] = __fmaf_rn(a3, b1, acc[3][1]);
            acc[3][2] = __fmaf_rn(a3, b2, acc[3][2]); acc[3][3] = __fmaf_rn(a3, b3, acc[3][3]);
        }
        __syncthreads();
        // end of a kc=512 depth block: fold block partial into total
        if (((k0 + BK) & (KC - 1)) == 0) {
#pragma unroll
            for (int i = 0; i < 4; i++)
#pragma unroll
                for (int j = 0; j < 4; j++) {
                    tot[i][j] = __fadd_rn(tot[i][j], acc[i][j]);
                    acc[i][j] = 0.0f;
                }
        }
    }
#pragma unroll
    for (int i = 0; i < 4; i++) {
        int b = bm + ty * 4 + i;
#pragma unroll
        for (int j = 0; j < 4; j++) {
            int h = bn + tx * 4 + j;
            int idx = b * Hd_ + h;
            float v = g_vh[idx], r = g_rh[idx];
            float spk = lif_step(tot[i][j], v, r);
            g_vh[idx] = v; g_rh[idx] = r; g_hid_spk[idx] = spk;
        }
    }
}

// -------------------- output GEMM (32x32 tile, kc=512 blocks) + fused LIF ---
#define OBM 32
#define OBN 32
#define OBK 32

__global__ __launch_bounds__(128) void k_gemm_out_lif(const float* __restrict__ W2,
                                                      float* __restrict__ out) {
    __shared__ float As[OBK][OBM + 1];
    __shared__ float Bs[OBK][OBN + 1];
    const int bn = blockIdx.x * OBN;    // over Out_
    const int bm = blockIdx.y * OBM;    // over Bsz
    const int tid = threadIdx.x;        // 128 threads
    const int tx = tid & 7;             // 8  -> 8*4 = 32 cols
    const int ty = tid >> 3;            // 16 -> 16*2 = 32 rows
    float tot[2][4] = {};
    float acc[2][4] = {};

    for (int k0 = 0; k0 < Hd_; k0 += OBK) {
#pragma unroll
        for (int p = 0; p < 8; p++) {
            int e = p * 128 + tid;
            int m = e >> 5, k = e & 31;
            As[k][m] = g_hid_spk[(bm + m) * Hd_ + k0 + k];
        }
#pragma unroll
        for (int p = 0; p < 8; p++) {
            int e = p * 128 + tid;
            int n = e >> 5, k = e & 31;
            Bs[k][n] = W2[(bn + n) * Hd_ + k0 + k];
        }
        __syncthreads();
#pragma unroll
        for (int k = 0; k < OBK; k++) {
            float a0 = As[k][ty * 2 + 0], a1 = As[k][ty * 2 + 1];
            float b0 = Bs[k][tx * 4 + 0], b1 = Bs[k][tx * 4 + 1];
            float b2 = Bs[k][tx * 4 + 2], b3 = Bs[k][tx * 4 + 3];
            acc[0][0] = __fmaf_rn(a0, b0, acc[0][0]); acc[0][1] = __fmaf_rn(a0, b1, acc[0][1]);
            acc[0][2] = __fmaf_rn(a0, b2, acc[0][2]); acc[0][3] = __fmaf_rn(a0, b3, acc[0][3]);
            acc[1][0] = __fmaf_rn(a1, b0, acc[1][0]); acc[1][1] = __fmaf_rn(a1, b1, acc[1][1]);
            acc[1][2] = __fmaf_rn(a1, b2, acc[1][2]); acc[1][3] = __fmaf_rn(a1, b3, acc[1][3]);
        }
        __syncthreads();
        if (((k0 + OBK) & (KC - 1)) == 0) {
#pragma unroll
            for (int i = 0; i < 2; i++)
#pragma unroll
                for (int j = 0; j < 4; j++) {
                    tot[i][j] = __fadd_rn(tot[i][j], acc[i][j]);
                    acc[i][j] = 0.0f;
                }
        }
    }
#pragma unroll
    for (int i = 0; i < 2; i++) {
        int b = bm + ty * 2 + i;
#pragma unroll
        for (int j = 0; j < 4; j++) {
            int o = bn + tx * 4 + j;
            int idx = b * Out_ + o;
            float v = g_vo[idx], r = g_ro[idx];
            float spk = lif_step(tot[i][j], v, r);
            g_vo[idx] = v; g_ro[idx] = r;
            out[idx] = __fadd_rn(out[idx], spk);
        }
    }
}

// -------------------- STDP (every 10th step) ---------------------------------
__global__ void k_pre() {
    int i = blockIdx.x * blockDim.x + threadIdx.x;     // In_
    float s = 0.0f;
    for (int b = 0; b < Bsz; b++) s = __fadd_rn(s, g_in_spk[b * In_ + i]);  // exact ints
    float pm = __fmul_rn(s, 0.0078125f);               // /128 exact
    g_pre[i] = pm;
    g_tp[i] = __fadd_rn(__fmul_rn(0.9f, g_tp[i]), pm);
}

__global__ void k_post() {
    int h = blockIdx.x * blockDim.x + threadIdx.x;     // Hd_
    float s = 0.0f;
    for (int b = 0; b < Bsz; b++) s = __fadd_rn(s, g_hid_spk[b * Hd_ + h]);
    float pm = __fmul_rn(s, 0.0078125f);
    g_post[h] = pm;
    g_tn[h] = __fadd_rn(__fmul_rn(0.9f, g_tn[h]), pm);
}

__global__ void k_both() {
    __shared__ float bufp[256], bufh[256];
    int tid = threadIdx.x;
    float sp = 0.0f, sh = 0.0f;
    for (int i = tid; i < In_; i += 256) sp += g_pre[i];
    for (int i = tid; i < Hd_; i += 256) sh += g_post[i];
    bufp[tid] = sp; bufh[tid] = sh;
    __syncthreads();
    for (int s = 128; s > 0; s >>= 1) {
        if (tid < s) { bufp[tid] += bufp[tid + s]; bufh[tid] += bufh[tid + s]; }
        __syncthreads();
    }
    if (tid == 0) g_both[0] = (bufp[0] > 0.0f && bufh[0] > 0.0f) ? 1.0f : 0.0f;
}

// W1[h,i] += LR*(tp[i]*post[h] - pre[i]*tn[h]), clip, gated by `both`.
__global__ void k_wupd() {
    if (g_both[0] == 0.0f) return;
    int idx = blockIdx.x * blockDim.x + threadIdx.x;   // Hd_*In_
    int h = idx >> 10;          // / In_
    int i = idx & (In_ - 1);    // % In_
    float d = __fmul_rn(LR, __fsub_rn(__fmul_rn(g_tp[i], g_post[h]),
                                      __fmul_rn(g_pre[i], g_tn[h])));
    float w = __fadd_rn(g_W1[idx], d);
    g_W1[idx] = fminf(fmaxf(w, -1.0f), 1.0f);
}

// -------------------- final scale --------------------------------------------
__global__ void k_scale(float* __restrict__ out) {
    int idx = blockIdx.x * blockDim.x + threadIdx.x;
    out[idx] = __fdiv_rn(out[idx], 100.0f);
}

// -------------------- launch --------------------------------------------------
extern "C" void kernel_launch(void* const* d_in, const int* in_sizes, int n_in,
                              void* d_out, int out_size) {
    const float* x     = (const float*)d_in[0];   // (B, In)
    const float* W1    = (const float*)d_in[1];   // (H, In)
    const float* W2    = (const float*)d_in[2];   // (Out, H)
    const float* noise = (const float*)d_in[3];   // (T, B, In)
    float* out = (float*)d_out;                   // (B, Out)

    k_init<<<(Bsz * Hd_) / 256, 256>>>(out);
    k_copyW1<<<(Hd_ * In_) / 256, 256>>>(W1);

    for (int t = 0; t < T_; t++) {
        k_input<<<(Bsz * In_) / 256, 256>>>(x, noise + (size_t)t * Bsz * In_);

        bool stdp = (t % 10) == 0;
        if (stdp) k_pre<<<In_ / 256, 256>>>();

        k_gemm_hid_lif<<<dim3(Hd_ / BN, Bsz / BM), 256>>>();

        if (stdp) {
            k_post<<<Hd_ / 256, 256>>>();
            k_both<<<1, 256>>>();
            k_wupd<<<(Hd_ * In_) / 256, 256>>>();
        }

        k_gemm_out_lif<<<dim3(Out_ / OBN, Bsz / OBM), 128>>>(W2, out);
    }

    k_scale<<<(Bsz * Out_) / 256, 256>>>(out);
}

// round 6
// speedup vs baseline: 9.4387x; 9.4387x over previous
#include <cuda_runtime.h>

// ---------------------------------------------------------------------------
// SpikingNeuralNetwork: 100-step LIF sim, sparse-gather formulation.
// Spikes are exactly 0/1, so within each Eigen kc=512 depth block the dense
// ascending-k FMA chain is bit-identical to an ascending-index __fadd_rn
// gather of weight rows. Block partials folded sequentially (matches the
// passing R5 dense kernel bit-for-bit). Elementwise math strictly rounded.
// B=128, In=1024, H=4096, Out=1024, T=100.
// ---------------------------------------------------------------------------

#define Bsz  128
#define In_  1024
#define Hd_  4096
#define Out_ 1024
#define T_   100
#define KC   512
#define NIB  2      // In_/KC  input k-blocks
#define NHB  8      // Hd_/KC  hidden k-blocks

#define THRESH 1.0f
#define DECAY  0.95f
#define REFRAC 2.0f
#define LR     0.001f

// -------------------- persistent device state -------------------------------
__device__ float g_vi[Bsz * In_];
__device__ float g_ri[Bsz * In_];
__device__ float g_vh[Bsz * Hd_];
__device__ float g_rh[Bsz * Hd_];
__device__ float g_vo[Bsz * Out_];
__device__ float g_ro[Bsz * Out_];
__device__ float g_W1T[In_ * Hd_];    // [i][h]  (STDP-updated in place)
__device__ float g_W2T[Hd_ * Out_];   // [h][o]
__device__ float g_in_spk[Bsz * In_];   // dense, for k_pre
__device__ float g_hid_spk[Bsz * Hd_];  // dense, for k_post
__device__ int   g_in_idx[Bsz][NIB][KC];
__device__ int   g_in_cnt[Bsz][NIB];
__device__ int   g_hid_idx[Bsz][NHB][KC];
__device__ int   g_hid_cnt[Bsz][NHB];
__device__ float g_tp[In_];
__device__ float g_tn[Hd_];
__device__ float g_pre[In_];
__device__ float g_post[Hd_];
__device__ float g_both[1];

// -------------------- LIF: strictly rounded (no FMA contraction) -----------
__device__ __forceinline__ float lif_step(float I, float& v, float& r) {
    bool active = I > 0.0f;
    bool refrac = r > 0.0f;
    float v_int = __fadd_rn(__fmul_rn(v, DECAY), I);
    bool fired = active && !refrac && (v_int >= THRESH);
    float v_new = !active ? v : ((refrac || fired) ? 0.0f : v_int);
    float r_new = !active ? r : (refrac ? __fsub_rn(r, 1.0f) : (fired ? REFRAC : r));
    v = v_new;
    r = r_new;
    return fired ? 1.0f : 0.0f;
}

// -------------------- init ---------------------------------------------------
__global__ void k_init(float* __restrict__ out) {
    int idx = blockIdx.x * blockDim.x + threadIdx.x;   // covers Bsz*Hd_
    if (idx < Bsz * In_)  { g_vi[idx] = 0.0f; g_ri[idx] = 0.0f; }
    if (idx < Bsz * Out_) { g_vo[idx] = 0.0f; g_ro[idx] = 0.0f; out[idx] = 0.0f; }
    if (idx < Bsz * Hd_)  { g_vh[idx] = 0.0f; g_rh[idx] = 0.0f; }
    if (idx < In_) g_tp[idx] = 0.0f;
    if (idx < Hd_) g_tn[idx] = 0.0f;
    if (idx == 0)  g_both[0] = 0.0f;
}

// transposes write __device__ globals directly (NEVER passed from host!)
__global__ void k_trW1(const float* __restrict__ W1) {   // [Hd_][In_] -> g_W1T [In_][Hd_]
    __shared__ float t[32][33];
    int i = blockIdx.x * 32 + threadIdx.x;
    int h = blockIdx.y * 32 + threadIdx.y;
    t[threadIdx.y][threadIdx.x] = W1[h * In_ + i];
    __syncthreads();
    int i2 = blockIdx.x * 32 + threadIdx.y;
    int h2 = blockIdx.y * 32 + threadIdx.x;
    g_W1T[(size_t)i2 * Hd_ + h2] = t[threadIdx.x][threadIdx.y];
}

__global__ void k_trW2(const float* __restrict__ W2) {   // [Out_][Hd_] -> g_W2T [Hd_][Out_]
    __shared__ float t[32][33];
    int h = blockIdx.x * 32 + threadIdx.x;
    int o = blockIdx.y * 32 + threadIdx.y;
    t[threadIdx.y][threadIdx.x] = W2[o * Hd_ + h];
    __syncthreads();
    int h2 = blockIdx.x * 32 + threadIdx.y;
    int o2 = blockIdx.y * 32 + threadIdx.x;
    g_W2T[(size_t)h2 * Out_ + o2] = t[threadIdx.x][threadIdx.y];
}

// -------------------- encode + input LIF + per-512-block compaction ---------
// grid (Bsz), 64 threads: warp w compacts k-block w (ascending order).
__global__ void k_input(const float* __restrict__ x,
                        const float* __restrict__ noise_t) {
    int b = blockIdx.x;
    int w = threadIdx.x >> 5;
    int lane = threadIdx.x & 31;
    int cnt = 0;
    for (int c = 0; c < KC / 32; c++) {
        int i = w * KC + c * 32 + lane;
        int idx = b * In_ + i;
        float p = fminf(fmaxf(__fmul_rn(x[idx], 100.0f), 0.0f), 100.0f);
        p = __fmul_rn(p, 0.001f);
        float I = (noise_t[idx] < p) ? 1.0f : 0.0f;
        float v = g_vi[idx], r = g_ri[idx];
        float spk = lif_step(I, v, r);
        g_vi[idx] = v; g_ri[idx] = r; g_in_spk[idx] = spk;
        unsigned m = __ballot_sync(0xffffffffu, spk > 0.0f);
        if (spk > 0.0f)
            g_in_idx[b][w][cnt + __popc(m & ((1u << lane) - 1u))] = i;
        cnt += __popc(m);
    }
    if (lane == 0) g_in_cnt[b][w] = cnt;
}

// -------------------- hidden layer: gather + LIF + compaction ----------------
// grid (NHB=8, Bsz): CTA owns 512 h-cols (= one hidden kc-block) for one b.
// 128 threads x 4 contiguous cols (float4).
__global__ __launch_bounds__(128) void k_hid() {
    __shared__ int sidx[In_];
    __shared__ int scnt[NIB];
    __shared__ unsigned char sflag[KC];
    const int b = blockIdx.y;
    const int h0 = blockIdx.x * KC;
    const int t = threadIdx.x;

    if (t < NIB) scnt[t] = g_in_cnt[b][t];
    __syncthreads();
    const int c0 = scnt[0], c1 = scnt[1];
    for (int j = t; j < c0; j += 128) sidx[j] = g_in_idx[b][0][j];
    for (int j = t; j < c1; j += 128) sidx[KC + j] = g_in_idx[b][1][j];
    __syncthreads();

    const int hcol = h0 + t * 4;
    float tx = 0.0f, ty = 0.0f, tz = 0.0f, tw = 0.0f;
#pragma unroll
    for (int kb = 0; kb < NIB; kb++) {
        const int cc = (kb == 0) ? c0 : c1;
        const int off = kb * KC;
        float px = 0.0f, py = 0.0f, pz = 0.0f, pw = 0.0f;
        int j = 0;
        for (; j + 4 <= cc; j += 4) {
            const float4 w0 = *(const float4*)(g_W1T + (size_t)sidx[off + j + 0] * Hd_ + hcol);
            const float4 w1 = *(const float4*)(g_W1T + (size_t)sidx[off + j + 1] * Hd_ + hcol);
            const float4 w2 = *(const float4*)(g_W1T + (size_t)sidx[off + j + 2] * Hd_ + hcol);
            const float4 w3 = *(const float4*)(g_W1T + (size_t)sidx[off + j + 3] * Hd_ + hcol);
            px = __fadd_rn(px, w0.x); py = __fadd_rn(py, w0.y); pz = __fadd_rn(pz, w0.z); pw = __fadd_rn(pw, w0.w);
            px = __fadd_rn(px, w1.x); py = __fadd_rn(py, w1.y); pz = __fadd_rn(pz, w1.z); pw = __fadd_rn(pw, w1.w);
            px = __fadd_rn(px, w2.x); py = __fadd_rn(py, w2.y); pz = __fadd_rn(pz, w2.z); pw = __fadd_rn(pw, w2.w);
            px = __fadd_rn(px, w3.x); py = __fadd_rn(py, w3.y); pz = __fadd_rn(pz, w3.z); pw = __fadd_rn(pw, w3.w);
        }
        for (; j < cc; j++) {
            const float4 w0 = *(const float4*)(g_W1T + (size_t)sidx[off + j] * Hd_ + hcol);
            px = __fadd_rn(px, w0.x); py = __fadd_rn(py, w0.y); pz = __fadd_rn(pz, w0.z); pw = __fadd_rn(pw, w0.w);
        }
        tx = __fadd_rn(tx, px); ty = __fadd_rn(ty, py);
        tz = __fadd_rn(tz, pz); tw = __fadd_rn(tw, pw);
    }

    float I4[4] = {tx, ty, tz, tw};
    float spk4[4];
#pragma unroll
    for (int c = 0; c < 4; c++) {
        int idx = b * Hd_ + hcol + c;
        float v = g_vh[idx], r = g_rh[idx];
        spk4[c] = lif_step(I4[c], v, r);
        g_vh[idx] = v; g_rh[idx] = r;
        sflag[t * 4 + c] = (spk4[c] > 0.0f) ? 1 : 0;
    }
    *(float4*)(g_hid_spk + (size_t)b * Hd_ + hcol) =
        make_float4(spk4[0], spk4[1], spk4[2], spk4[3]);
    __syncthreads();

    // warp 0: ordered compaction of this CTA's 512 hidden spikes
    if (t < 32) {
        int cnt = 0;
        for (int c = 0; c < KC / 32; c++) {
            int hh = c * 32 + t;
            int f = sflag[hh];
            unsigned m = __ballot_sync(0xffffffffu, f != 0);
            if (f) g_hid_idx[b][blockIdx.x][cnt + __popc(m & ((1u << t) - 1u))] = h0 + hh;
            cnt += __popc(m);
        }
        if (t == 0) g_hid_cnt[b][blockIdx.x] = cnt;
    }
}

// -------------------- output layer: gather + LIF + accumulation --------------
// grid (Bsz), 256 threads x 4 contiguous cols (covers Out_=1024).
__global__ __launch_bounds__(256) void k_out(float* __restrict__ out) {
    __shared__ int sidx[KC];
    const int b = blockIdx.x;
    const int t = threadIdx.x;
    const int ocol = t * 4;

    float tx = 0.0f, ty = 0.0f, tz = 0.0f, tw = 0.0f;
    for (int kb = 0; kb < NHB; kb++) {
        const int cnt = g_hid_cnt[b][kb];
        __syncthreads();                       // protect sidx reuse
        for (int j = t; j < cnt; j += 256) sidx[j] = g_hid_idx[b][kb][j];
        __syncthreads();
        float px = 0.0f, py = 0.0f, pz = 0.0f, pw = 0.0f;
        int j = 0;
        for (; j + 4 <= cnt; j += 4) {
            const float4 w0 = *(const float4*)(g_W2T + (size_t)sidx[j + 0] * Out_ + ocol);
            const float4 w1 = *(const float4*)(g_W2T + (size_t)sidx[j + 1] * Out_ + ocol);
            const float4 w2 = *(const float4*)(g_W2T + (size_t)sidx[j + 2] * Out_ + ocol);
            const float4 w3 = *(const float4*)(g_W2T + (size_t)sidx[j + 3] * Out_ + ocol);
            px = __fadd_rn(px, w0.x); py = __fadd_rn(py, w0.y); pz = __fadd_rn(pz, w0.z); pw = __fadd_rn(pw, w0.w);
            px = __fadd_rn(px, w1.x); py = __fadd_rn(py, w1.y); pz = __fadd_rn(pz, w1.z); pw = __fadd_rn(pw, w1.w);
            px = __fadd_rn(px, w2.x); py = __fadd_rn(py, w2.y); pz = __fadd_rn(pz, w2.z); pw = __fadd_rn(pw, w2.w);
            px = __fadd_rn(px, w3.x); py = __fadd_rn(py, w3.y); pz = __fadd_rn(pz, w3.z); pw = __fadd_rn(pw, w3.w);
        }
        for (; j < cnt; j++) {
            const float4 w0 = *(const float4*)(g_W2T + (size_t)sidx[j] * Out_ + ocol);
            px = __fadd_rn(px, w0.x); py = __fadd_rn(py, w0.y); pz = __fadd_rn(pz, w0.z); pw = __fadd_rn(pw, w0.w);
        }
        tx = __fadd_rn(tx, px); ty = __fadd_rn(ty, py);
        tz = __fadd_rn(tz, pz); tw = __fadd_rn(tw, pw);
    }

    float I4[4] = {tx, ty, tz, tw};
#pragma unroll
    for (int c = 0; c < 4; c++) {
        int idx = b * Out_ + ocol + c;
        float v = g_vo[idx], r = g_ro[idx];
        float spk = lif_step(I4[c], v, r);
        g_vo[idx] = v; g_ro[idx] = r;
        out[idx] = __fadd_rn(out[idx], spk);
    }
}

// -------------------- STDP (every 10th step) ---------------------------------
__global__ void k_pre() {
    int i = blockIdx.x * blockDim.x + threadIdx.x;     // In_
    float s = 0.0f;
    for (int b = 0; b < Bsz; b++) s = __fadd_rn(s, g_in_spk[b * In_ + i]);
    float pm = __fmul_rn(s, 0.0078125f);               // /128 exact
    g_pre[i] = pm;
    g_tp[i] = __fadd_rn(__fmul_rn(0.9f, g_tp[i]), pm);
}

__global__ void k_post() {
    int h = blockIdx.x * blockDim.x + threadIdx.x;     // Hd_
    float s = 0.0f;
    for (int b = 0; b < Bsz; b++) s = __fadd_rn(s, g_hid_spk[b * Hd_ + h]);
    float pm = __fmul_rn(s, 0.0078125f);
    g_post[h] = pm;
    g_tn[h] = __fadd_rn(__fmul_rn(0.9f, g_tn[h]), pm);
}

__global__ void k_both() {
    int lane = threadIdx.x;
    int si = 0, sh = 0;
    const int* ic = &g_in_cnt[0][0];
    const int* hc = &g_hid_cnt[0][0];
    for (int j = lane; j < Bsz * NIB; j += 32) si += ic[j];
    for (int j = lane; j < Bsz * NHB; j += 32) sh += hc[j];
    for (int o = 16; o; o >>= 1) {
        si += __shfl_down_sync(0xffffffffu, si, o);
        sh += __shfl_down_sync(0xffffffffu, sh, o);
    }
    if (lane == 0) g_both[0] = (si > 0 && sh > 0) ? 1.0f : 0.0f;
}

// W1T[i,h] += LR*(tp[i]*post[h] - pre[i]*tn[h]), clip, gated by `both`.
__global__ void k_wupd() {
    if (g_both[0] == 0.0f) return;
    int idx = blockIdx.x * blockDim.x + threadIdx.x;   // In_*Hd_
    int i = idx >> 12;            // / Hd_
    int h = idx & (Hd_ - 1);      // % Hd_
    float d = __fmul_rn(LR, __fsub_rn(__fmul_rn(g_tp[i], g_post[h]),
                                      __fmul_rn(g_pre[i], g_tn[h])));
    float w = __fadd_rn(g_W1T[idx], d);
    g_W1T[idx] = fminf(fmaxf(w, -1.0f), 1.0f);
}

// -------------------- final scale --------------------------------------------
__global__ void k_scale(float* __restrict__ out) {
    int idx = blockIdx.x * blockDim.x + threadIdx.x;
    out[idx] = __fdiv_rn(out[idx], 100.0f);
}

// -------------------- launch --------------------------------------------------
extern "C" void kernel_launch(void* const* d_in, const int* in_sizes, int n_in,
                              void* d_out, int out_size) {
    const float* x     = (const float*)d_in[0];   // (B, In)
    const float* W1    = (const float*)d_in[1];   // (H, In)
    const float* W2    = (const float*)d_in[2];   // (Out, H)
    const float* noise = (const float*)d_in[3];   // (T, B, In)
    float* out = (float*)d_out;                   // (B, Out)

    k_init<<<(Bsz * Hd_) / 256, 256>>>(out);
    k_trW1<<<dim3(In_ / 32, Hd_ / 32), dim3(32, 32)>>>(W1);
    k_trW2<<<dim3(Hd_ / 32, Out_ / 32), dim3(32, 32)>>>(W2);

    for (int t = 0; t < T_; t++) {
        k_input<<<Bsz, 64>>>(x, noise + (size_t)t * Bsz * In_);

        bool stdp = (t % 10) == 0;
        if (stdp) k_pre<<<In_ / 256, 256>>>();

        k_hid<<<dim3(NHB, Bsz), 128>>>();

        if (stdp) {
            k_post<<<Hd_ / 256, 256>>>();
            k_both<<<1, 32>>>();
            k_wupd<<<(In_ * Hd_) / 256, 256>>>();
        }

        k_out<<<Bsz, 256>>>(out);
    }

    k_scale<<<(Bsz * Out_) / 256, 256>>>(out);
}

// round 7
// speedup vs baseline: 12.0192x; 1.2734x over previous
#include <cuda_runtime.h>

// ---------------------------------------------------------------------------
// SpikingNeuralNetwork: 100-step LIF sim, sparse-gather formulation.
// Spikes are exactly 0/1, so within each Eigen kc=512 depth block the dense
// ascending-k FMA chain is bit-identical to an ascending-index __fadd_rn
// gather of weight rows. Block partials folded sequentially. Elementwise math
// strictly rounded. k_input is a fully parallel block-scan compaction.
// B=128, In=1024, H=4096, Out=1024, T=100.
// ---------------------------------------------------------------------------

#define Bsz  128
#define In_  1024
#define Hd_  4096
#define Out_ 1024
#define T_   100
#define KC   512
#define NIB  2      // In_/KC  input k-blocks
#define NHB  8      // Hd_/KC  hidden k-blocks

#define THRESH 1.0f
#define DECAY  0.95f
#define REFRAC 2.0f
#define LR     0.001f

// -------------------- persistent device state -------------------------------
__device__ float g_vi[Bsz * In_];
__device__ float g_ri[Bsz * In_];
__device__ float g_vh[Bsz * Hd_];
__device__ float g_rh[Bsz * Hd_];
__device__ float g_vo[Bsz * Out_];
__device__ float g_ro[Bsz * Out_];
__device__ float g_W1T[In_ * Hd_];    // [i][h]  (STDP-updated in place)
__device__ float g_W2T[Hd_ * Out_];   // [h][o]
__device__ float g_in_spk[Bsz * In_];   // dense, for k_pre
__device__ float g_hid_spk[Bsz * Hd_];  // dense, for k_post
__device__ int   g_in_idx[Bsz][NIB][KC];
__device__ int   g_in_cnt[Bsz][NIB];
__device__ int   g_hid_idx[Bsz][NHB][KC];
__device__ int   g_hid_cnt[Bsz][NHB];
__device__ float g_tp[In_];
__device__ float g_tn[Hd_];
__device__ float g_pre[In_];
__device__ float g_post[Hd_];
__device__ float g_both[1];

// -------------------- LIF: strictly rounded (no FMA contraction) -----------
__device__ __forceinline__ float lif_step(float I, float& v, float& r) {
    bool active = I > 0.0f;
    bool refrac = r > 0.0f;
    float v_int = __fadd_rn(__fmul_rn(v, DECAY), I);
    bool fired = active && !refrac && (v_int >= THRESH);
    float v_new = !active ? v : ((refrac || fired) ? 0.0f : v_int);
    float r_new = !active ? r : (refrac ? __fsub_rn(r, 1.0f) : (fired ? REFRAC : r));
    v = v_new;
    r = r_new;
    return fired ? 1.0f : 0.0f;
}

// -------------------- init ---------------------------------------------------
__global__ void k_init(float* __restrict__ out) {
    int idx = blockIdx.x * blockDim.x + threadIdx.x;   // covers Bsz*Hd_
    if (idx < Bsz * In_)  { g_vi[idx] = 0.0f; g_ri[idx] = 0.0f; }
    if (idx < Bsz * Out_) { g_vo[idx] = 0.0f; g_ro[idx] = 0.0f; out[idx] = 0.0f; }
    if (idx < Bsz * Hd_)  { g_vh[idx] = 0.0f; g_rh[idx] = 0.0f; }
    if (idx < In_) g_tp[idx] = 0.0f;
    if (idx < Hd_) g_tn[idx] = 0.0f;
    if (idx == 0)  g_both[0] = 0.0f;
}

// transposes write __device__ globals directly (NEVER passed from host!)
__global__ void k_trW1(const float* __restrict__ W1) {   // [Hd_][In_] -> g_W1T [In_][Hd_]
    __shared__ float t[32][33];
    int i = blockIdx.x * 32 + threadIdx.x;
    int h = blockIdx.y * 32 + threadIdx.y;
    t[threadIdx.y][threadIdx.x] = W1[h * In_ + i];
    __syncthreads();
    int i2 = blockIdx.x * 32 + threadIdx.y;
    int h2 = blockIdx.y * 32 + threadIdx.x;
    g_W1T[(size_t)i2 * Hd_ + h2] = t[threadIdx.x][threadIdx.y];
}

__global__ void k_trW2(const float* __restrict__ W2) {   // [Out_][Hd_] -> g_W2T [Hd_][Out_]
    __shared__ float t[32][33];
    int h = blockIdx.x * 32 + threadIdx.x;
    int o = blockIdx.y * 32 + threadIdx.y;
    t[threadIdx.y][threadIdx.x] = W2[o * Hd_ + h];
    __syncthreads();
    int h2 = blockIdx.x * 32 + threadIdx.y;
    int o2 = blockIdx.y * 32 + threadIdx.x;
    g_W2T[(size_t)h2 * Out_ + o2] = t[threadIdx.x][threadIdx.y];
}

// -------------------- encode + input LIF + parallel compaction ---------------
// grid (NIB, Bsz), 512 threads: one element per thread, block-scan compaction.
// Order within each (b, kc-block) stays ascending -> bit-identical lists.
__global__ __launch_bounds__(512) void k_input(const float* __restrict__ x,
                                               const float* __restrict__ noise_t) {
    __shared__ int woff[17];
    const int b = blockIdx.y;
    const int kb = blockIdx.x;
    const int t = threadIdx.x;
    const int wid = t >> 5;
    const int lane = t & 31;

    const int i = kb * KC + t;
    const int idx = b * In_ + i;
    float p = fminf(fmaxf(__fmul_rn(x[idx], 100.0f), 0.0f), 100.0f);
    p = __fmul_rn(p, 0.001f);
    float I = (noise_t[idx] < p) ? 1.0f : 0.0f;
    float v = g_vi[idx], r = g_ri[idx];
    float spk = lif_step(I, v, r);
    g_vi[idx] = v; g_ri[idx] = r; g_in_spk[idx] = spk;

    unsigned m = __ballot_sync(0xffffffffu, spk > 0.0f);
    if (lane == 0) woff[wid + 1] = __popc(m);   // counts staged at [1..16]
    __syncthreads();
    if (t == 0) {
        int s = 0;
        woff[0] = 0;
#pragma unroll
        for (int w = 1; w <= 16; w++) { s += woff[w]; woff[w] = s; }
        g_in_cnt[b][kb] = s;
    }
    __syncthreads();
    if (spk > 0.0f)
        g_in_idx[b][kb][woff[wid] + __popc(m & ((1u << lane) - 1u))] = i;
}

// -------------------- hidden layer: gather + LIF + compaction ----------------
// grid (NHB=8, Bsz): CTA owns 512 h-cols (= one hidden kc-block) for one b.
// 128 threads x 4 contiguous cols (float4).
__global__ __launch_bounds__(128) void k_hid() {
    __shared__ int sidx[In_];
    __shared__ int scnt[NIB];
    __shared__ unsigned char sflag[KC];
    const int b = blockIdx.y;
    const int h0 = blockIdx.x * KC;
    const int t = threadIdx.x;

    if (t < NIB) scnt[t] = g_in_cnt[b][t];
    __syncthreads();
    const int c0 = scnt[0], c1 = scnt[1];
    for (int j = t; j < c0; j += 128) sidx[j] = g_in_idx[b][0][j];
    for (int j = t; j < c1; j += 128) sidx[KC + j] = g_in_idx[b][1][j];
    __syncthreads();

    const int hcol = h0 + t * 4;
    float tx = 0.0f, ty = 0.0f, tz = 0.0f, tw = 0.0f;
#pragma unroll
    for (int kb = 0; kb < NIB; kb++) {
        const int cc = (kb == 0) ? c0 : c1;
        const int off = kb * KC;
        float px = 0.0f, py = 0.0f, pz = 0.0f, pw = 0.0f;
        int j = 0;
        for (; j + 4 <= cc; j += 4) {
            const float4 w0 = *(const float4*)(g_W1T + (size_t)sidx[off + j + 0] * Hd_ + hcol);
            const float4 w1 = *(const float4*)(g_W1T + (size_t)sidx[off + j + 1] * Hd_ + hcol);
            const float4 w2 = *(const float4*)(g_W1T + (size_t)sidx[off + j + 2] * Hd_ + hcol);
            const float4 w3 = *(const float4*)(g_W1T + (size_t)sidx[off + j + 3] * Hd_ + hcol);
            px = __fadd_rn(px, w0.x); py = __fadd_rn(py, w0.y); pz = __fadd_rn(pz, w0.z); pw = __fadd_rn(pw, w0.w);
            px = __fadd_rn(px, w1.x); py = __fadd_rn(py, w1.y); pz = __fadd_rn(pz, w1.z); pw = __fadd_rn(pw, w1.w);
            px = __fadd_rn(px, w2.x); py = __fadd_rn(py, w2.y); pz = __fadd_rn(pz, w2.z); pw = __fadd_rn(pw, w2.w);
            px = __fadd_rn(px, w3.x); py = __fadd_rn(py, w3.y); pz = __fadd_rn(pz, w3.z); pw = __fadd_rn(pw, w3.w);
        }
        for (; j < cc; j++) {
            const float4 w0 = *(const float4*)(g_W1T + (size_t)sidx[off + j] * Hd_ + hcol);
            px = __fadd_rn(px, w0.x); py = __fadd_rn(py, w0.y); pz = __fadd_rn(pz, w0.z); pw = __fadd_rn(pw, w0.w);
        }
        tx = __fadd_rn(tx, px); ty = __fadd_rn(ty, py);
        tz = __fadd_rn(tz, pz); tw = __fadd_rn(tw, pw);
    }

    float I4[4] = {tx, ty, tz, tw};
    float spk4[4];
#pragma unroll
    for (int c = 0; c < 4; c++) {
        int idx = b * Hd_ + hcol + c;
        float v = g_vh[idx], r = g_rh[idx];
        spk4[c] = lif_step(I4[c], v, r);
        g_vh[idx] = v; g_rh[idx] = r;
        sflag[t * 4 + c] = (spk4[c] > 0.0f) ? 1 : 0;
    }
    *(float4*)(g_hid_spk + (size_t)b * Hd_ + hcol) =
        make_float4(spk4[0], spk4[1], spk4[2], spk4[3]);
    __syncthreads();

    // warp 0: ordered compaction of this CTA's 512 hidden spikes
    if (t < 32) {
        int cnt = 0;
        for (int c = 0; c < KC / 32; c++) {
            int hh = c * 32 + t;
            int f = sflag[hh];
            unsigned m = __ballot_sync(0xffffffffu, f != 0);
            if (f) g_hid_idx[b][blockIdx.x][cnt + __popc(m & ((1u << t) - 1u))] = h0 + hh;
            cnt += __popc(m);
        }
        if (t == 0) g_hid_cnt[b][blockIdx.x] = cnt;
    }
}

// -------------------- output layer: gather + LIF + accumulation --------------
// grid (Bsz), 256 threads x 4 contiguous cols (covers Out_=1024).
__global__ __launch_bounds__(256) void k_out(float* __restrict__ out) {
    __shared__ int sidx[KC];
    const int b = blockIdx.x;
    const int t = threadIdx.x;
    const int ocol = t * 4;

    float tx = 0.0f, ty = 0.0f, tz = 0.0f, tw = 0.0f;
    for (int kb = 0; kb < NHB; kb++) {
        const int cnt = g_hid_cnt[b][kb];
        __syncthreads();                       // protect sidx reuse
        for (int j = t; j < cnt; j += 256) sidx[j] = g_hid_idx[b][kb][j];
        __syncthreads();
        float px = 0.0f, py = 0.0f, pz = 0.0f, pw = 0.0f;
        int j = 0;
        for (; j + 4 <= cnt; j += 4) {
            const float4 w0 = *(const float4*)(g_W2T + (size_t)sidx[j + 0] * Out_ + ocol);
            const float4 w1 = *(const float4*)(g_W2T + (size_t)sidx[j + 1] * Out_ + ocol);
            const float4 w2 = *(const float4*)(g_W2T + (size_t)sidx[j + 2] * Out_ + ocol);
            const float4 w3 = *(const float4*)(g_W2T + (size_t)sidx[j + 3] * Out_ + ocol);
            px = __fadd_rn(px, w0.x); py = __fadd_rn(py, w0.y); pz = __fadd_rn(pz, w0.z); pw = __fadd_rn(pw, w0.w);
            px = __fadd_rn(px, w1.x); py = __fadd_rn(py, w1.y); pz = __fadd_rn(pz, w1.z); pw = __fadd_rn(pw, w1.w);
            px = __fadd_rn(px, w2.x); py = __fadd_rn(py, w2.y); pz = __fadd_rn(pz, w2.z); pw = __fadd_rn(pw, w2.w);
            px = __fadd_rn(px, w3.x); py = __fadd_rn(py, w3.y); pz = __fadd_rn(pz, w3.z); pw = __fadd_rn(pw, w3.w);
        }
        for (; j < cnt; j++) {
            const float4 w0 = *(const float4*)(g_W2T + (size_t)sidx[j] * Out_ + ocol);
            px = __fadd_rn(px, w0.x); py = __fadd_rn(py, w0.y); pz = __fadd_rn(pz, w0.z); pw = __fadd_rn(pw, w0.w);
        }
        tx = __fadd_rn(tx, px); ty = __fadd_rn(ty, py);
        tz = __fadd_rn(tz, pz); tw = __fadd_rn(tw, pw);
    }

    float I4[4] = {tx, ty, tz, tw};
#pragma unroll
    for (int c = 0; c < 4; c++) {
        int idx = b * Out_ + ocol + c;
        float v = g_vo[idx], r = g_ro[idx];
        float spk = lif_step(I4[c], v, r);
        g_vo[idx] = v; g_ro[idx] = r;
        out[idx] = __fadd_rn(out[idx], spk);
    }
}

// -------------------- STDP (every 10th step) ---------------------------------
__global__ void k_pre() {
    int i = blockIdx.x * blockDim.x + threadIdx.x;     // In_
    float s = 0.0f;
    for (int b = 0; b < Bsz; b++) s = __fadd_rn(s, g_in_spk[b * In_ + i]);
    float pm = __fmul_rn(s, 0.0078125f);               // /128 exact
    g_pre[i] = pm;
    g_tp[i] = __fadd_rn(__fmul_rn(0.9f, g_tp[i]), pm);
}

__global__ void k_post() {
    int h = blockIdx.x * blockDim.x + threadIdx.x;     // Hd_
    float s = 0.0f;
    for (int b = 0; b < Bsz; b++) s = __fadd_rn(s, g_hid_spk[b * Hd_ + h]);
    float pm = __fmul_rn(s, 0.0078125f);
    g_post[h] = pm;
    g_tn[h] = __fadd_rn(__fmul_rn(0.9f, g_tn[h]), pm);
}

__global__ void k_both() {
    int lane = threadIdx.x;
    int si = 0, sh = 0;
    const int* ic = &g_in_cnt[0][0];
    const int* hc = &g_hid_cnt[0][0];
    for (int j = lane; j < Bsz * NIB; j += 32) si += ic[j];
    for (int j = lane; j < Bsz * NHB; j += 32) sh += hc[j];
    for (int o = 16; o; o >>= 1) {
        si += __shfl_down_sync(0xffffffffu, si, o);
        sh += __shfl_down_sync(0xffffffffu, sh, o);
    }
    if (lane == 0) g_both[0] = (si > 0 && sh > 0) ? 1.0f : 0.0f;
}

// W1T[i,h] += LR*(tp[i]*post[h] - pre[i]*tn[h]), clip, gated by `both`.
__global__ void k_wupd() {
    if (g_both[0] == 0.0f) return;
    int idx = blockIdx.x * blockDim.x + threadIdx.x;   // In_*Hd_
    int i = idx >> 12;            // / Hd_
    int h = idx & (Hd_ - 1);      // % Hd_
    float d = __fmul_rn(LR, __fsub_rn(__fmul_rn(g_tp[i], g_post[h]),
                                      __fmul_rn(g_pre[i], g_tn[h])));
    float w = __fadd_rn(g_W1T[idx], d);
    g_W1T[idx] = fminf(fmaxf(w, -1.0f), 1.0f);
}

// -------------------- final scale --------------------------------------------
__global__ void k_scale(float* __restrict__ out) {
    int idx = blockIdx.x * blockDim.x + threadIdx.x;
    out[idx] = __fdiv_rn(out[idx], 100.0f);
}

// -------------------- launch --------------------------------------------------
extern "C" void kernel_launch(void* const* d_in, const int* in_sizes, int n_in,
                              void* d_out, int out_size) {
    const float* x     = (const float*)d_in[0];   // (B, In)
    const float* W1    = (const float*)d_in[1];   // (H, In)
    const float* W2    = (const float*)d_in[2];   // (Out, H)
    const float* noise = (const float*)d_in[3];   // (T, B, In)
    float* out = (float*)d_out;                   // (B, Out)

    k_init<<<(Bsz * Hd_) / 256, 256>>>(out);
    k_trW1<<<dim3(In_ / 32, Hd_ / 32), dim3(32, 32)>>>(W1);
    k_trW2<<<dim3(Hd_ / 32, Out_ / 32), dim3(32, 32)>>>(W2);

    for (int t = 0; t < T_; t++) {
        k_input<<<dim3(NIB, Bsz), 512>>>(x, noise + (size_t)t * Bsz * In_);

        bool stdp = (t % 10) == 0;
        if (stdp) k_pre<<<In_ / 256, 256>>>();

        k_hid<<<dim3(NHB, Bsz), 128>>>();

        if (stdp) {
            k_post<<<Hd_ / 256, 256>>>();
            k_both<<<1, 32>>>();
            k_wupd<<<(In_ * Hd_) / 256, 256>>>();
        }

        k_out<<<Bsz, 256>>>(out);
    }

    k_scale<<<(Bsz * Out_) / 256, 256>>>(out);
}